// round 17
// baseline (speedup 1.0000x reference)
#include <cuda_runtime.h>
#include <cuda_fp16.h>
#include <cstdint>

#define IN_F   8192
#define OUT_F  8192
#define NBLK   64
#define M_TILE 32
#define GRID_Y 6
#define TOT_TILES 256               // 8192 / 32 token tiles per feature block

#define ROW_B   272                 // fp16 padded row stride bytes
#define W_B     (128 * ROW_B)       // 34816
#define XROW_B  544                 // fp32 X padded row stride bytes (136 floats)
#define XSTG    (M_TILE * XROW_B)   // 17408 per stage
#define NSTAGE  2

#define OFF_BIAS 0
#define OFF_W    1024
#define OFF_X    (1024 + W_B)               // 35840
#define SMEM_TOTAL (OFF_X + NSTAGE * XSTG)  // 70656 -> 3 CTAs/SM (212KB)

// pre-converted W blocks: [b] -> 128x128 fp16 padded tile
__device__ __align__(16) char g_wcvt[NBLK * W_B];

__device__ __forceinline__ uint32_t smem_u32(const void* p) {
    uint32_t a;
    asm("{ .reg .u64 t; cvta.to.shared.u64 t, %1; cvt.u32.u64 %0, t; }" : "=r"(a) : "l"(p));
    return a;
}
__device__ __forceinline__ uint32_t pack_h2(float a, float b) {
    __half2 h = __float22half2_rn(make_float2(a, b));
    return *reinterpret_cast<uint32_t*>(&h);
}
__device__ __forceinline__ float2 lds64(uint32_t a) {
    float2 v;
    asm volatile("ld.shared.v2.f32 {%0,%1}, [%2];" : "=f"(v.x), "=f"(v.y) : "r"(a));
    return v;
}
__device__ __forceinline__ void ldsm_x4(uint32_t& r0, uint32_t& r1, uint32_t& r2, uint32_t& r3,
                                        uint32_t addr) {
    asm volatile("ldmatrix.sync.aligned.m8n8.x4.shared.b16 {%0,%1,%2,%3}, [%4];"
                 : "=r"(r0), "=r"(r1), "=r"(r2), "=r"(r3) : "r"(addr));
}
__device__ __forceinline__ void mma_f16(float* d, const uint32_t* a, uint32_t b0, uint32_t b1) {
    asm volatile(
        "mma.sync.aligned.m16n8k16.row.col.f32.f16.f16.f32 "
        "{%0,%1,%2,%3}, {%4,%5,%6,%7}, {%8,%9}, {%0,%1,%2,%3};"
        : "+f"(d[0]), "+f"(d[1]), "+f"(d[2]), "+f"(d[3])
        : "r"(a[0]), "r"(a[1]), "r"(a[2]), "r"(a[3]), "r"(b0), "r"(b1));
}
__device__ __forceinline__ float wire_act(float z) {
    float s, e;
    asm("sin.approx.ftz.f32 %0, %1;" : "=f"(s) : "f"(z * 30.0f));
    float t = -0.01442695040888963f * z * z;   // -0.01 * log2(e) * z^2
    asm("ex2.approx.ftz.f32 %0, %1;" : "=f"(e) : "f"(t));
    return s * e;
}
__device__ __forceinline__ void stg_cs_v2(float* p, float a, float b) {
    asm volatile("st.global.cs.v2.f32 [%0], {%1,%2};" :: "l"(p), "f"(a), "f"(b) : "memory");
}

// ------------- prep: convert W diag blocks to fp16 padded tiles -------------
__global__ void __launch_bounds__(128)
wcvt_kernel(const float* __restrict__ w)
{
    const int b = blockIdx.x;
    const int t = threadIdx.x;
    const int r0 = t >> 5;
    const int c4 = t & 31;
    const float* wrow = w + (size_t)(b * 128) * IN_F + (size_t)b * 128;
    char* dst = g_wcvt + (size_t)b * W_B;
    #pragma unroll 4
    for (int r = r0; r < 128; r += 4) {
        float4 v = *(const float4*)(wrow + (size_t)r * IN_F + (c4 << 2));
        *(uint2*)(dst + r * ROW_B + (c4 << 3)) =
            make_uint2(pack_h2(v.x, v.y), pack_h2(v.z, v.w));
    }
}

// ------------- main kernel: hybrid-B, 3 CTAs/SM, 2-stage cp.async X -------------
__global__ void __launch_bounds__(256, 3)
siren_occ3_kernel(const float* __restrict__ x, const float* __restrict__ bias,
                  float* __restrict__ out)
{
    extern __shared__ char smem[];
    const uint32_t sbase = smem_u32(smem);
    const int tid = threadIdx.x;
    const int wid = tid >> 5;
    const int lid = tid & 31;
    const int b = blockIdx.x;

    const int yi = blockIdx.y;
    const int tstart = (TOT_TILES * yi) / GRID_Y;
    const int tend   = (TOT_TILES * (yi + 1)) / GRID_Y;
    const int ntiles = tend - tstart;

    // ---- W tile via cp.async (group 0) ----
    {
        const char* wsrc = g_wcvt + (size_t)b * W_B;
        #pragma unroll 9
        for (int i = tid; i < W_B / 16; i += 256) {
            uint32_t dst = sbase + OFF_W + i * 16;
            asm volatile("cp.async.cg.shared.global [%0], [%1], 16;"
                         :: "r"(dst), "l"(wsrc + i * 16) : "memory");
        }
        asm volatile("cp.async.commit_group;" ::: "memory");
    }
    if (tid < 128) ((float*)(smem + OFF_BIAS))[tid] = bias[b * 128 + tid];

    const float* xbase = x + (size_t)b * 128;
    #define ISSUE_X(tj_, buf_)                                                    \
        {                                                                         \
            const float* src_ = xbase + (size_t)((tj_) * M_TILE) * IN_F;          \
            const uint32_t db_ = sbase + OFF_X + (buf_) * XSTG;                   \
            _Pragma("unroll")                                                     \
            for (int j_ = 0; j_ < 4; j_++) {                                      \
                int c_ = tid + j_ * 256;                                          \
                int r_ = c_ >> 5, o_ = c_ & 31;                                   \
                asm volatile("cp.async.cg.shared.global [%0], [%1], 16;"          \
                             :: "r"(db_ + r_ * XROW_B + o_ * 16),                 \
                                "l"(src_ + (size_t)r_ * IN_F + o_ * 4) : "memory"); \
            }                                                                     \
        }

    ISSUE_X(tstart + 0, 0);
    asm volatile("cp.async.commit_group;" ::: "memory");
    ISSUE_X(tstart + 1, 1);
    asm volatile("cp.async.commit_group;" ::: "memory");

    // ---- warp tiling: 8 warps -> 2 (m16) x 4 (n32) ----
    const int M0 = (wid & 1) * 16;
    const int N0 = (wid >> 1) * 32;
    const uint32_t offB = (uint32_t)((((lid >> 4) & 1) * 8 + (lid & 7)) * ROW_B
                                     + ((lid >> 3) & 1) * 16);
    const uint32_t bB = sbase + OFF_W + (uint32_t)(N0 * ROW_B) + offB;
    const uint32_t aoff = (uint32_t)((M0 + (lid >> 2)) * XROW_B + (lid & 3) * 8);
    const float* bs = (const float*)(smem + OFF_BIAS);
    const int lrow = lid >> 2;
    const int lcol = (lid & 3) * 2;

    // ---- hoist B fragments for ks 0..3 only (32 regs) ----
    asm volatile("cp.async.wait_group 2;" ::: "memory");   // W retired
    __syncthreads();
    uint32_t breg[4][8];
    #pragma unroll
    for (int ks = 0; ks < 4; ks++) {
        const uint32_t kb = (uint32_t)(ks * 32);
        ldsm_x4(breg[ks][0], breg[ks][1], breg[ks][2], breg[ks][3], bB + kb);
        ldsm_x4(breg[ks][4], breg[ks][5], breg[ks][6], breg[ks][7],
                bB + kb + (uint32_t)(16 * ROW_B));
    }

    #pragma unroll 1
    for (int i = 0; i < ntiles; i++) {
        asm volatile("cp.async.wait_group 1;" ::: "memory");   // X_i done
        __syncthreads();

        const uint32_t aS = sbase + OFF_X + (i & 1) * XSTG + aoff;

        float acc[4][4];
        #pragma unroll
        for (int nt = 0; nt < 4; nt++)
            #pragma unroll
            for (int k = 0; k < 4; k++) acc[nt][k] = 0.0f;

        // ks 0..3: B from registers
        #pragma unroll
        for (int ks = 0; ks < 4; ks++) {
            const uint32_t ka = (uint32_t)(ks * 64);
            float2 A0 = lds64(aS + ka);
            float2 A1 = lds64(aS + ka + 8 * XROW_B);
            float2 A2 = lds64(aS + ka + 32);
            float2 A3 = lds64(aS + ka + 8 * XROW_B + 32);
            uint32_t af[4];
            af[0] = pack_h2(A0.x, A0.y);
            af[1] = pack_h2(A1.x, A1.y);
            af[2] = pack_h2(A2.x, A2.y);
            af[3] = pack_h2(A3.x, A3.y);
            mma_f16(acc[0], af, breg[ks][0], breg[ks][1]);
            mma_f16(acc[1], af, breg[ks][2], breg[ks][3]);
            mma_f16(acc[2], af, breg[ks][4], breg[ks][5]);
            mma_f16(acc[3], af, breg[ks][6], breg[ks][7]);
        }
        // ks 4..7: B from smem (ldmatrix in-loop, low live range)
        #pragma unroll
        for (int ks = 4; ks < 8; ks++) {
            const uint32_t ka = (uint32_t)(ks * 64);
            const uint32_t kb = (uint32_t)(ks * 32);
            float2 A0 = lds64(aS + ka);
            float2 A1 = lds64(aS + ka + 8 * XROW_B);
            float2 A2 = lds64(aS + ka + 32);
            float2 A3 = lds64(aS + ka + 8 * XROW_B + 32);
            uint32_t af[4];
            af[0] = pack_h2(A0.x, A0.y);
            af[1] = pack_h2(A1.x, A1.y);
            af[2] = pack_h2(A2.x, A2.y);
            af[3] = pack_h2(A3.x, A3.y);
            uint32_t bq[4];
            ldsm_x4(bq[0], bq[1], bq[2], bq[3], bB + kb);
            mma_f16(acc[0], af, bq[0], bq[1]);
            mma_f16(acc[1], af, bq[2], bq[3]);
            ldsm_x4(bq[0], bq[1], bq[2], bq[3], bB + kb + (uint32_t)(16 * ROW_B));
            mma_f16(acc[2], af, bq[0], bq[1]);
            mma_f16(acc[3], af, bq[2], bq[3]);
        }

        __syncthreads();                     // all warps done reading buf i&1
        if (i + 2 < ntiles) ISSUE_X(tstart + i + 2, i & 1);
        asm volatile("cp.async.commit_group;" ::: "memory");

        // ---- epilogue: bias + wire activation + streaming store ----
        const int rbase = (tstart + i) * M_TILE + M0 + lrow;
        #pragma unroll
        for (int nt = 0; nt < 4; nt++) {
            const int nn = N0 + nt * 8 + lcol;
            float* p0 = out + (size_t)rbase * OUT_F + (size_t)b * 128 + nn;
            stg_cs_v2(p0, wire_act(acc[nt][0] + bs[nn]), wire_act(acc[nt][1] + bs[nn + 1]));
            stg_cs_v2(p0 + (size_t)8 * OUT_F,
                      wire_act(acc[nt][2] + bs[nn]), wire_act(acc[nt][3] + bs[nn + 1]));
        }
    }
}

extern "C" void kernel_launch(void* const* d_in, const int* in_sizes, int n_in,
                              void* d_out, int out_size)
{
    const float* x    = (const float*)d_in[0];
    const float* w    = (const float*)d_in[1];
    const float* bias = (const float*)d_in[2];
    float* out = (float*)d_out;

    wcvt_kernel<<<NBLK, 128>>>(w);

    cudaFuncSetAttribute(siren_occ3_kernel,
                         cudaFuncAttributeMaxDynamicSharedMemorySize, SMEM_TOTAL);
    dim3 grid(NBLK, GRID_Y);
    siren_occ3_kernel<<<grid, 256, SMEM_TOTAL>>>(x, bias, out);
}